// round 1
// baseline (speedup 1.0000x reference)
#include <cuda_runtime.h>

#define Bsz  4096
#define Tn   512
#define Fdim 4
#define Hn   50
#define Gn   200      // 4*H, torch gate order: i, f, g, o
#define TB   32       // batch tile per CTA (== warp width)
#define NT   256      // threads per CTA (8 warps)
#define RPW  25       // gate rows per warp (200 / 8)
#define WSTR 52       // padded weight row stride (floats), 16B-aligned rows

// shared layout (floats)
#define OFF_WIH0 0                       // 200*4   = 800
#define OFF_WHH0 (OFF_WIH0 + Gn*Fdim)    // 200*52  = 10400
#define OFF_WIH1 (OFF_WHH0 + Gn*WSTR)
#define OFF_WHH1 (OFF_WIH1 + Gn*WSTR)
#define OFF_B0   (OFF_WHH1 + Gn*WSTR)    // 200
#define OFF_B1   (OFF_B0 + Gn)           // 200
#define OFF_G    (OFF_B1 + Gn)           // 200*32 = 6400
#define OFF_H0   (OFF_G + Gn*TB)         // 50*32  = 1600
#define OFF_C0   (OFF_H0 + Hn*TB)
#define OFF_H1   (OFF_C0 + Hn*TB)
#define OFF_C1   (OFF_H1 + Hn*TB)
#define SMEM_FLOATS (OFF_C1 + Hn*TB)
#define SMEM_BYTES  (SMEM_FLOATS * 4)

__device__ __forceinline__ float sigf(float x) {
    // accurate sigmoid: EX2-based expf + approx reciprocal (~1e-7 rel)
    return __fdividef(1.0f, 1.0f + __expf(-x));
}
__device__ __forceinline__ float tanhf_acc(float x) {
    // tanh(x) = 2*sigmoid(2x) - 1 (exact identity)
    return fmaf(2.0f, sigf(2.0f * x), -1.0f);
}

__global__ void __launch_bounds__(NT, 1) lstm2_kernel(
    const float* __restrict__ x,
    const float* __restrict__ Wih0, const float* __restrict__ Whh0,
    const float* __restrict__ bih0, const float* __restrict__ bhh0,
    const float* __restrict__ Wih1, const float* __restrict__ Whh1,
    const float* __restrict__ bih1, const float* __restrict__ bhh1,
    const float* __restrict__ fcW,  const float* __restrict__ fcb,
    float* __restrict__ out)
{
    extern __shared__ float sm[];
    float* sWih0 = sm + OFF_WIH0;
    float* sWhh0 = sm + OFF_WHH0;
    float* sWih1 = sm + OFF_WIH1;
    float* sWhh1 = sm + OFF_WHH1;
    float* sB0   = sm + OFF_B0;
    float* sB1   = sm + OFF_B1;
    float* sG    = sm + OFF_G;
    float* sH0   = sm + OFF_H0;
    float* sC0   = sm + OFF_C0;
    float* sH1   = sm + OFF_H1;
    float* sC1   = sm + OFF_C1;

    const int tid = threadIdx.x;

    // ---- stage weights / biases, zero state ----
    for (int i = tid; i < Gn * Fdim; i += NT) sWih0[i] = Wih0[i];
    for (int i = tid; i < Gn * Hn; i += NT) {
        int g = i / Hn, k = i - g * Hn;
        sWhh0[g * WSTR + k] = Whh0[i];
        sWih1[g * WSTR + k] = Wih1[i];
        sWhh1[g * WSTR + k] = Whh1[i];
    }
    for (int i = tid; i < Gn; i += NT) {
        sB0[i] = bih0[i] + bhh0[i];
        sB1[i] = bih1[i] + bhh1[i];
    }
    for (int i = tid; i < Hn * TB; i += NT) {
        sH0[i] = 0.f; sC0[i] = 0.f; sH1[i] = 0.f; sC1[i] = 0.f;
    }
    __syncthreads();

    const int w    = tid >> 5;
    const int lane = tid & 31;
    const int g0   = w * RPW;
    const int bg   = blockIdx.x * TB + lane;        // global batch index of this lane
    const float* xb = x + (size_t)bg * Tn * Fdim;

    float4 xv = *(const float4*)xb;                 // x at t=0
    float4 xnext = xv;

    float h[Hn];

    for (int t = 0; t < Tn; ++t) {
        // prefetch next step's x (latency hidden under the gate GEMVs)
        if (t + 1 < Tn) xnext = *(const float4*)(xb + (size_t)(t + 1) * Fdim);

        // ---- layer 0 gates: b + Wih0*x + Whh0*h0 ----
        #pragma unroll
        for (int k = 0; k < Hn; ++k) h[k] = sH0[k * TB + lane];
        #pragma unroll 5
        for (int r = 0; r < RPW; ++r) {
            int g = g0 + r;
            const float* wr = sWhh0 + g * WSTR;
            const float* wi = sWih0 + g * Fdim;
            float a0 = fmaf(wi[0], xv.x, sB0[g]);
            float a1 = wi[1] * xv.y;
            a0 = fmaf(wi[2], xv.z, a0);
            a1 = fmaf(wi[3], xv.w, a1);
            #pragma unroll
            for (int k = 0; k < Hn; k += 2) {
                a0 = fmaf(wr[k],     h[k],     a0);
                a1 = fmaf(wr[k + 1], h[k + 1], a1);
            }
            sG[g * TB + lane] = a0 + a1;
        }
        __syncthreads();

        // ---- layer 0 epilogue ----
        #pragma unroll 1
        for (int task = tid; task < Hn * TB; task += NT) {
            float gi = sG[task];
            float gf = sG[task + 50 * TB];
            float gg = sG[task + 100 * TB];
            float go = sG[task + 150 * TB];
            float c  = fmaf(sigf(gf), sC0[task], sigf(gi) * tanhf_acc(gg));
            sC0[task] = c;
            sH0[task] = sigf(go) * tanhf_acc(c);
        }
        __syncthreads();

        // ---- layer 1 gates, pass 1: b1 + Wih1*h0_new ----
        #pragma unroll
        for (int k = 0; k < Hn; ++k) h[k] = sH0[k * TB + lane];
        #pragma unroll 5
        for (int r = 0; r < RPW; ++r) {
            int g = g0 + r;
            const float* wr = sWih1 + g * WSTR;
            float a0 = sB0 ? sB1[g] : 0.f;  // sB1[g]
            float a1 = 0.f;
            #pragma unroll
            for (int k = 0; k < Hn; k += 2) {
                a0 = fmaf(wr[k],     h[k],     a0);
                a1 = fmaf(wr[k + 1], h[k + 1], a1);
            }
            sG[g * TB + lane] = a0 + a1;
        }
        // ---- layer 1 gates, pass 2: += Whh1*h1 (same thread, no sync needed) ----
        #pragma unroll
        for (int k = 0; k < Hn; ++k) h[k] = sH1[k * TB + lane];
        #pragma unroll 5
        for (int r = 0; r < RPW; ++r) {
            int g = g0 + r;
            const float* wr = sWhh1 + g * WSTR;
            float a0 = sG[g * TB + lane];
            float a1 = 0.f;
            #pragma unroll
            for (int k = 0; k < Hn; k += 2) {
                a0 = fmaf(wr[k],     h[k],     a0);
                a1 = fmaf(wr[k + 1], h[k + 1], a1);
            }
            sG[g * TB + lane] = a0 + a1;
        }
        __syncthreads();

        // ---- layer 1 epilogue ----
        #pragma unroll 1
        for (int task = tid; task < Hn * TB; task += NT) {
            float gi = sG[task];
            float gf = sG[task + 50 * TB];
            float gg = sG[task + 100 * TB];
            float go = sG[task + 150 * TB];
            float c  = fmaf(sigf(gf), sC1[task], sigf(gi) * tanhf_acc(gg));
            sC1[task] = c;
            sH1[task] = sigf(go) * tanhf_acc(c);
        }
        __syncthreads();

        xv = xnext;
    }

    // ---- final FC: out[b] = fcW @ hT + fcb  (4 outputs per batch) ----
    if (tid < TB * Fdim) {
        int b2 = tid >> 2, f = tid & 3;
        float a = fcb[f];
        #pragma unroll
        for (int j = 0; j < Hn; ++j)
            a = fmaf(fcW[f * Hn + j], sH1[j * TB + b2], a);
        out[((size_t)blockIdx.x * TB + b2) * Fdim + f] = a;
    }
}

extern "C" void kernel_launch(void* const* d_in, const int* in_sizes, int n_in,
                              void* d_out, int out_size) {
    const float* x    = (const float*)d_in[0];
    const float* Wih0 = (const float*)d_in[1];
    const float* Whh0 = (const float*)d_in[2];
    const float* bih0 = (const float*)d_in[3];
    const float* bhh0 = (const float*)d_in[4];
    const float* Wih1 = (const float*)d_in[5];
    const float* Whh1 = (const float*)d_in[6];
    const float* bih1 = (const float*)d_in[7];
    const float* bhh1 = (const float*)d_in[8];
    const float* fcW  = (const float*)d_in[9];
    const float* fcb  = (const float*)d_in[10];
    float* out = (float*)d_out;

    cudaFuncSetAttribute(lstm2_kernel,
                         cudaFuncAttributeMaxDynamicSharedMemorySize, SMEM_BYTES);
    lstm2_kernel<<<Bsz / TB, NT, SMEM_BYTES>>>(
        x, Wih0, Whh0, bih0, bhh0, Wih1, Whh1, bih1, bhh1, fcW, fcb, out);
}

// round 2
// speedup vs baseline: 1.1149x; 1.1149x over previous
#include <cuda_runtime.h>

#define Bsz   4096
#define Tn    512
#define Fdim  4
#define Hn    50
#define TB    32      // batch tile per CTA (== warp width)
#define NT    256     // 8 warps

// shared byte offsets (all 16B aligned)
#define O_Q0HH 0                    // [k][u][4] floats: 50*50*16 = 40000
#define O_Q1IH 40000                // 40000
#define O_Q1HH 80000                // 40000
#define O_Q0IH 120000               // [kf][u][4]: 4*50*16 = 3200
#define O_BQ0  123200               // [u][4]: 800
#define O_BQ1  124000               // 800
#define O_H0   124800               // 2 bufs x 50*32*4 = 12800
#define O_H1   137600               // 12800
#define SMEM_BYTES 150400
#define HBUF   6400                 // one h buffer, bytes

using u64 = unsigned long long;

__device__ __forceinline__ u64 pack2(float v) {
    u64 r; unsigned i = __float_as_uint(v);
    asm("mov.b64 %0, {%1, %1};" : "=l"(r) : "r"(i));
    return r;
}
__device__ __forceinline__ void unpack2(u64 v, float& a, float& b) {
    unsigned lo, hi;
    asm("mov.b64 {%0, %1}, %2;" : "=r"(lo), "=r"(hi) : "l"(v));
    a = __uint_as_float(lo); b = __uint_as_float(hi);
}
__device__ __forceinline__ void ffma2(u64& d, u64 a, u64 b) {
    asm("fma.rn.f32x2 %0, %1, %2, %0;" : "+l"(d) : "l"(a), "l"(b));
}
__device__ __forceinline__ void lds_v2b64(u64& a, u64& b, unsigned addr) {
    asm("ld.shared.v2.b64 {%0, %1}, [%2];" : "=l"(a), "=l"(b) : "r"(addr));
}
__device__ __forceinline__ float lds_f32(unsigned addr) {
    float v; asm("ld.shared.b32 %0, [%1];" : "=f"(v) : "r"(addr));
    return v;
}
__device__ __forceinline__ void sts_f32(unsigned addr, float v) {
    asm("st.shared.b32 [%0], %1;" :: "r"(addr), "f"(v));
}

__device__ __forceinline__ float sigf(float x) {
    return __fdividef(1.0f, 1.0f + __expf(-x));
}
__device__ __forceinline__ float tanhf_acc(float x) {
    return fmaf(2.0f, sigf(2.0f * x), -1.0f);   // exact identity
}

// Each thread: one batch (lane), U hidden units; c-state lives in registers.
template<int U>
__device__ __forceinline__ void run_loop(unsigned sb, int lane, int ubase,
                                         const float* __restrict__ xb)
{
    const unsigned a_q0hh = sb + O_Q0HH;
    const unsigned a_q1ih = sb + O_Q1IH;
    const unsigned a_q1hh = sb + O_Q1HH;
    const unsigned a_q0ih = sb + O_Q0IH;
    const unsigned a_bq0  = sb + O_BQ0;
    const unsigned a_bq1  = sb + O_BQ1;
    const unsigned a_h0   = sb + O_H0;
    const unsigned a_h1   = sb + O_H1;

    float c0[U], c1[U];
    #pragma unroll
    for (int u = 0; u < U; ++u) { c0[u] = 0.f; c1[u] = 0.f; }

    float4 xv = *(const float4*)xb;

    for (int t = 0; t < Tn; ++t) {
        float4 xn = xv;
        if (t + 1 < Tn) xn = *(const float4*)(xb + (size_t)(t + 1) * Fdim);
        const unsigned cur = (t & 1) ? HBUF : 0u;
        const unsigned nxt = HBUF - cur;

        u64 accA[U], accB[U];       // (i,f) and (g,o) packed accumulators

        // ---- layer 0 gates: bias + Wih0*x + Whh0*h0_prev ----
        #pragma unroll
        for (int u = 0; u < U; ++u)
            lds_v2b64(accA[u], accB[u], a_bq0 + (ubase + u) * 16);
        {
            u64 x0 = pack2(xv.x), x1 = pack2(xv.y), x2 = pack2(xv.z), x3 = pack2(xv.w);
            #pragma unroll
            for (int u = 0; u < U; ++u) {
                u64 wa, wb;
                lds_v2b64(wa, wb, a_q0ih + (0 * 50 + ubase + u) * 16);
                ffma2(accA[u], wa, x0); ffma2(accB[u], wb, x0);
                lds_v2b64(wa, wb, a_q0ih + (1 * 50 + ubase + u) * 16);
                ffma2(accA[u], wa, x1); ffma2(accB[u], wb, x1);
                lds_v2b64(wa, wb, a_q0ih + (2 * 50 + ubase + u) * 16);
                ffma2(accA[u], wa, x2); ffma2(accB[u], wb, x2);
                lds_v2b64(wa, wb, a_q0ih + (3 * 50 + ubase + u) * 16);
                ffma2(accA[u], wa, x3); ffma2(accB[u], wb, x3);
            }
        }
        {
            const unsigned hb = a_h0 + cur + lane * 4;
            #pragma unroll 2
            for (int k = 0; k < Hn; ++k) {
                u64 hd = pack2(lds_f32(hb + k * 128));
                const unsigned wk = a_q0hh + k * 800 + ubase * 16;
                #pragma unroll
                for (int u = 0; u < U; ++u) {
                    u64 wa, wb;
                    lds_v2b64(wa, wb, wk + u * 16);
                    ffma2(accA[u], wa, hd);
                    ffma2(accB[u], wb, hd);
                }
            }
        }
        // ---- layer 0 cell epilogue (c in registers, h -> shared[nxt]) ----
        #pragma unroll
        for (int u = 0; u < U; ++u) {
            float gi, gf, gg, go;
            unpack2(accA[u], gi, gf);
            unpack2(accB[u], gg, go);
            float c = fmaf(sigf(gf), c0[u], sigf(gi) * tanhf_acc(gg));
            c0[u] = c;
            sts_f32(a_h0 + nxt + (ubase + u) * 128 + lane * 4,
                    sigf(go) * tanhf_acc(c));
        }
        __syncthreads();   // single sync per step (hazards proven separated)

        // ---- layer 1 gates: bias + Wih1*h0_new + Whh1*h1_prev ----
        #pragma unroll
        for (int u = 0; u < U; ++u)
            lds_v2b64(accA[u], accB[u], a_bq1 + (ubase + u) * 16);
        {
            const unsigned h0b = a_h0 + nxt + lane * 4;
            const unsigned h1b = a_h1 + cur + lane * 4;
            #pragma unroll 2
            for (int k = 0; k < Hn; ++k) {
                u64 h0d = pack2(lds_f32(h0b + k * 128));
                u64 h1d = pack2(lds_f32(h1b + k * 128));
                const unsigned wk1 = a_q1ih + k * 800 + ubase * 16;
                const unsigned wk2 = a_q1hh + k * 800 + ubase * 16;
                #pragma unroll
                for (int u = 0; u < U; ++u) {
                    u64 wa, wb, wc, wd;
                    lds_v2b64(wa, wb, wk1 + u * 16);
                    lds_v2b64(wc, wd, wk2 + u * 16);
                    ffma2(accA[u], wa, h0d);
                    ffma2(accB[u], wb, h0d);
                    ffma2(accA[u], wc, h1d);
                    ffma2(accB[u], wd, h1d);
                }
            }
        }
        // ---- layer 1 cell epilogue ----
        #pragma unroll
        for (int u = 0; u < U; ++u) {
            float gi, gf, gg, go;
            unpack2(accA[u], gi, gf);
            unpack2(accB[u], gg, go);
            float c = fmaf(sigf(gf), c1[u], sigf(gi) * tanhf_acc(gg));
            c1[u] = c;
            sts_f32(a_h1 + nxt + (ubase + u) * 128 + lane * 4,
                    sigf(go) * tanhf_acc(c));
        }
        xv = xn;
    }
}

__global__ void __launch_bounds__(NT, 1) lstm2_kernel(
    const float* __restrict__ x,
    const float* __restrict__ Wih0, const float* __restrict__ Whh0,
    const float* __restrict__ bih0, const float* __restrict__ bhh0,
    const float* __restrict__ Wih1, const float* __restrict__ Whh1,
    const float* __restrict__ bih1, const float* __restrict__ bhh1,
    const float* __restrict__ fcW,  const float* __restrict__ fcb,
    float* __restrict__ out)
{
    extern __shared__ float sm[];
    const int tid = threadIdx.x;

    // ---- stage weights as per-unit gate quads [wi,wf,wg,wo] ----
    for (int i = tid; i < Hn * Hn; i += NT) {          // i = k*50 + u
        int k = i / Hn, u = i - k * Hn;
        float* q0 = sm + (O_Q0HH / 4) + i * 4;
        q0[0] = Whh0[(      u) * Hn + k];
        q0[1] = Whh0[( 50 + u) * Hn + k];
        q0[2] = Whh0[(100 + u) * Hn + k];
        q0[3] = Whh0[(150 + u) * Hn + k];
        float* q1i = sm + (O_Q1IH / 4) + i * 4;
        q1i[0] = Wih1[(      u) * Hn + k];
        q1i[1] = Wih1[( 50 + u) * Hn + k];
        q1i[2] = Wih1[(100 + u) * Hn + k];
        q1i[3] = Wih1[(150 + u) * Hn + k];
        float* q1h = sm + (O_Q1HH / 4) + i * 4;
        q1h[0] = Whh1[(      u) * Hn + k];
        q1h[1] = Whh1[( 50 + u) * Hn + k];
        q1h[2] = Whh1[(100 + u) * Hn + k];
        q1h[3] = Whh1[(150 + u) * Hn + k];
    }
    for (int i = tid; i < Fdim * Hn; i += NT) {        // i = kf*50 + u
        int kf = i / Hn, u = i - kf * Hn;
        float* q = sm + (O_Q0IH / 4) + i * 4;
        q[0] = Wih0[(      u) * Fdim + kf];
        q[1] = Wih0[( 50 + u) * Fdim + kf];
        q[2] = Wih0[(100 + u) * Fdim + kf];
        q[3] = Wih0[(150 + u) * Fdim + kf];
    }
    for (int u = tid; u < Hn; u += NT) {
        float* b0 = sm + (O_BQ0 / 4) + u * 4;
        b0[0] = bih0[u]       + bhh0[u];
        b0[1] = bih0[50 + u]  + bhh0[50 + u];
        b0[2] = bih0[100 + u] + bhh0[100 + u];
        b0[3] = bih0[150 + u] + bhh0[150 + u];
        float* b1 = sm + (O_BQ1 / 4) + u * 4;
        b1[0] = bih1[u]       + bhh1[u];
        b1[1] = bih1[50 + u]  + bhh1[50 + u];
        b1[2] = bih1[100 + u] + bhh1[100 + u];
        b1[3] = bih1[150 + u] + bhh1[150 + u];
    }
    for (int i = tid; i < 6400; i += NT)               // zero both h double-buffers
        sm[(O_H0 / 4) + i] = 0.f;
    __syncthreads();

    const int wid  = tid >> 5;
    const int lane = tid & 31;
    // units per warp: 7,7,6,6,6,6,6,6  -> per-SMSP load 13,13,12,12
    const int U     = (wid < 2) ? 7 : 6;
    const int ubase = (wid < 2) ? wid * 7 : 14 + (wid - 2) * 6;

    const unsigned sb = (unsigned)__cvta_generic_to_shared(sm);
    const float* xb = x + (size_t)(blockIdx.x * TB + lane) * Tn * Fdim;

    if (U == 7) run_loop<7>(sb, lane, ubase, xb);
    else        run_loop<6>(sb, lane, ubase, xb);

    __syncthreads();

    // final h1 is in buffer 0 (t=511: cur=1, nxt=0)
    if (tid < TB * Fdim) {
        int b2 = tid >> 2, f = tid & 3;
        float a = fcb[f];
        const float* h1 = sm + (O_H1 / 4);
        #pragma unroll
        for (int j = 0; j < Hn; ++j)
            a = fmaf(fcW[f * Hn + j], h1[j * TB + b2], a);
        out[((size_t)blockIdx.x * TB + b2) * Fdim + f] = a;
    }
}

extern "C" void kernel_launch(void* const* d_in, const int* in_sizes, int n_in,
                              void* d_out, int out_size) {
    const float* x    = (const float*)d_in[0];
    const float* Wih0 = (const float*)d_in[1];
    const float* Whh0 = (const float*)d_in[2];
    const float* bih0 = (const float*)d_in[3];
    const float* bhh0 = (const float*)d_in[4];
    const float* Wih1 = (const float*)d_in[5];
    const float* Whh1 = (const float*)d_in[6];
    const float* bih1 = (const float*)d_in[7];
    const float* bhh1 = (const float*)d_in[8];
    const float* fcW  = (const float*)d_in[9];
    const float* fcb  = (const float*)d_in[10];
    float* out = (float*)d_out;

    cudaFuncSetAttribute(lstm2_kernel,
                         cudaFuncAttributeMaxDynamicSharedMemorySize, SMEM_BYTES);
    lstm2_kernel<<<Bsz / TB, NT, SMEM_BYTES>>>(
        x, Wih0, Whh0, bih0, bhh0, Wih1, Whh1, bih1, bhh1, fcW, fcb, out);
}